// round 8
// baseline (speedup 1.0000x reference)
#include <cuda_runtime.h>
#include <cuda_fp16.h>
#include <cstdint>

#define BB 32
#define CC 64
#define HH 64
#define WW 64
#define EE 8
#define HWC (HH*WW)

// Scratch (device globals: no allocation allowed)
__device__ float        g_S[BB * 9 * CC];   // box sums [(b*9+k)*64+c], k=di*3+dj
__device__ int          g_cnt[BB];
__device__ volatile int g_flag[BB];
__device__ float        g_val[BB];
__device__ int          g_idx[BB];

// ===========================================================================
// helpers
// ===========================================================================
__device__ __forceinline__ uint32_t smem_u32(const void* p) {
    uint32_t a;
    asm("{ .reg .u64 t; cvta.to.shared.u64 t, %1; cvt.u32.u64 %0, t; }" : "=r"(a) : "l"(p));
    return a;
}

__device__ __forceinline__ uint32_t pack_f16x2(float even, float odd) {
    __half2 h = __floats2half2_rn(even, odd);
    return *reinterpret_cast<uint32_t*>(&h);
}

#define LDMATRIX_X2T(R, addr) \
    asm volatile("ldmatrix.sync.aligned.m8n8.x2.trans.shared.b16 {%0,%1}, [%2];" \
        : "=r"((R)[0]), "=r"((R)[1]) : "r"(addr))

#define MMA_F16(D, A, B0, B1) \
    asm volatile("mma.sync.aligned.m16n8k16.row.col.f32.f16.f16.f32 " \
        "{%0,%1,%2,%3}, {%4,%5,%6,%7}, {%8,%9}, {%0,%1,%2,%3};" \
        : "+f"((D)[0]), "+f"((D)[1]), "+f"((D)[2]), "+f"((D)[3]) \
        : "r"((A)[0]), "r"((A)[1]), "r"((A)[2]), "r"((A)[3]), "r"(B0), "r"(B1))

// ===========================================================================
// Kernel 0: zero the cross-block scratch (must be fresh every launch)
// ===========================================================================
__global__ void zero_kernel() {
    int i = blockIdx.x * blockDim.x + threadIdx.x;
    const int n = BB * 9 * CC;
    for (int j = i; j < n; j += gridDim.x * blockDim.x) g_S[j] = 0.f;
    if (i < BB) { g_cnt[i] = 0; g_flag[i] = 0; }
}

// ===========================================================================
// Fused kernel: x is read ONCE.
// Grid (chunk=0..31, b=0..31), b-major in linear bid -> whole batches resident.
// Phase 1: stage X tile (fp16, smem) + contribute box sums (atomics).
// Gate:    last block per b computes softmax/top-1, publishes val/idx.
// Phase 2: fp16 mma.sync GEMM from the staged tile.
// ===========================================================================
#define XPITCH 68u   // words per X row (64 data words + 4 pad)

__global__ __launch_bounds__(128) void fused_kernel(const float* __restrict__ x,
                                                    const float* __restrict__ expert_w,
                                                    const float* __restrict__ gate_w,
                                                    const float* __restrict__ gate_b,
                                                    float* __restrict__ out,
                                                    int write_ew) {
    __shared__ uint32_t sX[64 * XPITCH];     // fp16x2 X tile
    __shared__ float sCvA[64][3], sCvB[64][3];
    __shared__ float sGat[8];
    __shared__ float shv;
    __shared__ int   she, shLast;

    const int tid   = threadIdx.x;
    const int warp  = tid >> 5, lane = tid & 31;
    const int chunk = blockIdx.x;            // hw chunk: image rows 2c, 2c+1
    const int b     = blockIdx.y;
    const int hw0   = chunk * 128;

    const float* Xsrc = x + (size_t)b * CC * HWC + hw0;

    // ---- Phase 1: stage + row statistics ----
    // warp handles c = i*4 + warp each iter; lane = float4 within the 128-wide row.
    // lanes 0-15 cover image row r0=2*chunk, lanes 16-31 cover r1=2*chunk+1.
    #pragma unroll
    for (int i = 0; i < 16; i++) {
        int c = i * 4 + warp;
        float4 v = *(const float4*)(Xsrc + (size_t)c * HWC + lane * 4);
        uint2 wv;
        wv.x = pack_f16x2(v.x, v.y);
        wv.y = pack_f16x2(v.z, v.w);
        *(uint2*)(sX + c * XPITCH + lane * 2) = wv;

        float ps = (v.x + v.y) + (v.z + v.w);
        #pragma unroll
        for (int o = 8; o; o >>= 1) ps += __shfl_xor_sync(0xffffffffu, ps, o);  // sum within 16-lane half
        int srcL = lane & 16;
        float e0  = __shfl_sync(0xffffffffu, v.x, srcL);        // x[r][0]
        float e1  = __shfl_sync(0xffffffffu, v.y, srcL);        // x[r][1]
        float e62 = __shfl_sync(0xffffffffu, v.z, srcL + 15);   // x[r][62]
        float e63 = __shfl_sync(0xffffffffu, v.w, srcL + 15);   // x[r][63]
        if ((lane & 15) == 0) {
            float* dst = (lane < 16) ? sCvA[c] : sCvB[c];
            dst[0] = ps - e62 - e63;   // cols 0..61
            dst[1] = ps - e0  - e63;   // cols 1..62
            dst[2] = ps - e0  - e1;    // cols 2..63
        }
    }
    __syncthreads();

    // ---- contribute to box sums ----
    {
        int r0 = chunk * 2, r1 = r0 + 1;
        float mA[3] = { (r0 <= 61) ? 1.f : 0.f, (r0 >= 1 && r0 <= 62) ? 1.f : 0.f, (r0 >= 2) ? 1.f : 0.f };
        float mB[3] = { (r1 <= 61) ? 1.f : 0.f, (r1 >= 1 && r1 <= 62) ? 1.f : 0.f, (r1 >= 2) ? 1.f : 0.f };
        #pragma unroll
        for (int p = 0; p < 5; p++) {
            int j = tid + p * 128;
            if (j < 576) {
                int k = j >> 6, c = j & 63;      // k = di*3+dj
                int di = k / 3, dj = k - di * 3;
                float contrib = mA[di] * sCvA[c][dj] + mB[di] * sCvB[c][dj];
                atomicAdd(&g_S[(b * 9 + k) * CC + c], contrib);
            }
        }
    }
    __syncthreads();
    if (tid == 0) {
        __threadfence();
        int old = atomicAdd(&g_cnt[b], 1);
        shLast = (old == 31);
    }
    __syncthreads();

    if (shLast) {
        // ---- gate: this block sees all 32 contributions ----
        __threadfence();
        float a0 = 0.f, a1 = 0.f;
        for (int idx = lane; idx < 576; idx += 32) {
            int c = idx / 9, k = idx - c * 9;
            float s = g_S[(b * 9 + k) * CC + c];
            a0 += gate_w[warp * 576 + idx] * s;
            a1 += gate_w[(warp + 4) * 576 + idx] * s;
        }
        #pragma unroll
        for (int o = 16; o; o >>= 1) {
            a0 += __shfl_down_sync(0xffffffffu, a0, o);
            a1 += __shfl_down_sync(0xffffffffu, a1, o);
        }
        if (lane == 0) {
            sGat[warp]     = a0 + gate_b[warp] * 3844.0f;
            sGat[warp + 4] = a1 + gate_b[warp + 4] * 3844.0f;
        }
        __syncthreads();
        if (tid == 0) {
            float m = sGat[0]; int mi = 0;
            #pragma unroll
            for (int e2 = 1; e2 < 8; e2++) { if (sGat[e2] > m) { m = sGat[e2]; mi = e2; } }
            float s = 0.f;
            #pragma unroll
            for (int e2 = 0; e2 < 8; e2++) s += expf(sGat[e2] - m);
            float v_ = 1.0f / s;
            g_val[b] = v_;
            g_idx[b] = mi;
            shv = v_; she = mi;
            if (write_ew) {
                float* ew = out + BB * CC * HWC + b * 8;
                #pragma unroll
                for (int e2 = 0; e2 < 8; e2++) ew[e2] = (e2 == mi) ? v_ : 0.0f;
            }
            __threadfence();
            g_flag[b] = 1;
        }
        __syncthreads();
    } else {
        if (tid == 0) {
            while (g_flag[b] == 0) __nanosleep(64);
            shv = *((volatile float*)&g_val[b]);   // bypass L1 (line shared across b)
            she = *((volatile int*)&g_idx[b]);
        }
        __syncthreads();
    }
    const float val = shv;
    const int   e   = she;

    // ---- Phase 2: fp16 GEMM from the staged tile ----
    const int wf = warp >> 1;   // f group of 32
    const int wn = warp & 1;    // hw group of 64
    const uint32_t sxb = smem_u32(sX);

    uint32_t af[2][4][4];
    {
        const float* Wb = expert_w + (size_t)e * 4096;
        int rA = wf * 32 + (lane >> 2);
        int kA = (lane & 3) * 2;
        #pragma unroll
        for (int mt = 0; mt < 2; mt++) {
            int r0 = rA + mt * 16;
            #pragma unroll
            for (int kt = 0; kt < 4; kt++) {
                int k0 = kt * 16 + kA;
                float2 w0 = *(const float2*)(Wb + r0 * 64 + k0);
                float2 w1 = *(const float2*)(Wb + (r0 + 8) * 64 + k0);
                float2 w2 = *(const float2*)(Wb + r0 * 64 + k0 + 8);
                float2 w3 = *(const float2*)(Wb + (r0 + 8) * 64 + k0 + 8);
                af[mt][kt][0] = pack_f16x2(w0.x, w0.y);
                af[mt][kt][1] = pack_f16x2(w1.x, w1.y);
                af[mt][kt][2] = pack_f16x2(w2.x, w2.y);
                af[mt][kt][3] = pack_f16x2(w3.x, w3.y);
            }
        }
    }

    float acc[2][8][4];
    #pragma unroll
    for (int mt = 0; mt < 2; mt++)
        #pragma unroll
        for (int nt = 0; nt < 8; nt++)
            #pragma unroll
            for (int q = 0; q < 4; q++) acc[mt][nt][q] = 0.f;

    const uint32_t krow = (uint32_t)(lane & 15);
    #pragma unroll
    for (int kt = 0; kt < 4; kt++) {
        uint32_t kbase = ((uint32_t)(kt * 16) + krow) * (XPITCH * 4u);
        #pragma unroll
        for (int nt = 0; nt < 8; nt++) {
            uint32_t noff = (uint32_t)(wn * 64 + nt * 8) * 2u;
            uint32_t bf[2];
            LDMATRIX_X2T(bf, sxb + kbase + noff);
            #pragma unroll
            for (int mt = 0; mt < 2; mt++)
                MMA_F16(acc[mt][nt], af[mt][kt], bf[0], bf[1]);
        }
    }

    // ---- epilogue: streaming stores ----
    float* outb = out + (size_t)b * CC * HWC + hw0;
    int rbase = wf * 32 + (lane >> 2);
    int cbase = wn * 64 + (lane & 3) * 2;
    #pragma unroll
    for (int mt = 0; mt < 2; mt++) {
        #pragma unroll
        for (int nt = 0; nt < 8; nt++) {
            int f0 = rbase + mt * 16;
            int cc = cbase + nt * 8;
            float2 v0 = make_float2(acc[mt][nt][0] * val, acc[mt][nt][1] * val);
            float2 v1 = make_float2(acc[mt][nt][2] * val, acc[mt][nt][3] * val);
            __stcs((float2*)(outb + (size_t)f0 * HWC + cc),       v0);
            __stcs((float2*)(outb + (size_t)(f0 + 8) * HWC + cc), v1);
        }
    }
}

// ===========================================================================
extern "C" void kernel_launch(void* const* d_in, const int* in_sizes, int n_in,
                              void* d_out, int out_size) {
    const float* x = nullptr, *gate_w = nullptr, *gate_b = nullptr, *expert_w = nullptr;
    for (int i = 0; i < n_in; i++) {
        switch (in_sizes[i]) {
            case BB*CC*HH*WW: x        = (const float*)d_in[i]; break;  // 524288
            case EE*CC*3*3:   gate_w   = (const float*)d_in[i]; break;  // 4608
            case EE:          gate_b   = (const float*)d_in[i]; break;  // 8
            case EE*CC*CC:    expert_w = (const float*)d_in[i]; break;  // 32768
            default: break;
        }
    }
    float* out = (float*)d_out;
    const int main_elems = BB * CC * HH * WW;
    int write_ew = (out_size >= main_elems + BB * EE) ? 1 : 0;

    zero_kernel<<<36, 512>>>();
    fused_kernel<<<dim3(HWC / 128, BB), 128>>>(x, expert_w, gate_w, gate_b, out, write_ew);
}